// round 2
// baseline (speedup 1.0000x reference)
#include <cuda_runtime.h>
#include <math.h>
#include <stdint.h>

// Problem constants
#define Bb   4
#define SS   4096
#define HH   2048
#define DFFC 8192
#define BSZ  (Bb*SS)          // 16384 tokens
#define EPS_F 1e-5f

typedef unsigned long long ull;

// ---------------- scratch (device globals; no allocation allowed) ----------
__device__ float g_logits[BSZ];
__device__ float g_r1[BSZ];
__device__ float g_thr[Bb];
__device__ int   g_sel[BSZ];
__device__ int   g_nsel;
__device__ float g_Wcomb[(size_t)HH*HH];        // diag(n1w)*Wv*Wo
__device__ float g_res[(size_t)BSZ*HH];         // residual for selected tokens
__device__ float g_r2[BSZ];
__device__ float g_hbuf[(size_t)BSZ*DFFC];      // silu(gate)*up

// ---------------- f32x2 helpers -------------------------------------------
__device__ __forceinline__ void ffma2(ull &c, ull a, ull b){
    asm("fma.rn.f32x2 %0,%1,%2,%0;" : "+l"(c) : "l"(a), "l"(b));
}
__device__ __forceinline__ ull pack2(float v){
    ull r; asm("mov.b64 %0,{%1,%1};" : "=l"(r) : "f"(v)); return r;
}
__device__ __forceinline__ float2 unpack2(ull v){
    float2 r; asm("mov.b64 {%0,%1},%2;" : "=f"(r.x), "=f"(r.y) : "l"(v)); return r;
}

// ---------------- router: logits (fp64 accum) + rmsnorm1 scale -------------
__global__ __launch_bounds__(256) void k_router(const float* __restrict__ x,
        const float* __restrict__ wr, const float* __restrict__ br){
    int t = blockIdx.x;
    const float* xr = x + (size_t)t*HH;
    double ds = 0.0; float ssq = 0.f;
    for (int i = threadIdx.x; i < HH; i += 256){
        float v = xr[i];
        ds += (double)v * (double)wr[i];
        ssq += v*v;
    }
    __shared__ double sd[256];
    __shared__ float  sf[256];
    sd[threadIdx.x] = ds; sf[threadIdx.x] = ssq;
    __syncthreads();
    for (int o = 128; o > 0; o >>= 1){
        if (threadIdx.x < o){ sd[threadIdx.x] += sd[threadIdx.x+o]; sf[threadIdx.x] += sf[threadIdx.x+o]; }
        __syncthreads();
    }
    if (threadIdx.x == 0){
        g_logits[t] = (float)(sd[0] + (double)br[0]);
        g_r1[t]     = rsqrtf(sf[0]*(1.f/HH) + EPS_F);
    }
}

// ---------------- per-batch threshold via bitonic sort ---------------------
__global__ __launch_bounds__(1024) void k_topk(){
    __shared__ float s[SS];
    int b = blockIdx.x, tid = threadIdx.x;
    for (int i = tid; i < SS; i += 1024) s[i] = g_logits[b*SS + i];
    __syncthreads();
    for (int k = 2; k <= SS; k <<= 1){
        for (int j = k >> 1; j > 0; j >>= 1){
            for (int i = tid; i < SS; i += 1024){
                int ixj = i ^ j;
                if (ixj > i){
                    float a = s[i], c = s[ixj];
                    bool up = ((i & k) == 0);
                    if ((a > c) == up){ s[i] = c; s[ixj] = a; }
                }
            }
            __syncthreads();
        }
    }
    if (tid == 0) g_thr[b] = s[SS/2];   // k-th largest of 4096, k=2048
}

__global__ void k_zero(){ g_nsel = 0; }

__global__ __launch_bounds__(256) void k_compact(){
    int t = blockIdx.x*256 + threadIdx.x;
    if (t < BSZ && g_logits[t] >= g_thr[t/SS]){
        int p = atomicAdd(&g_nsel, 1);
        g_sel[p] = t;
    }
}

// ---------------- GEMM cores: 128x128x16 tiles, 256 thr, 8x8/thr, f32x2 ----
// K4: Wcomb = diag(n1w)*Wv @ Wo   (M=N=K=2048)
__global__ __launch_bounds__(256,2) void k_wcomb(const float* __restrict__ Wv,
        const float* __restrict__ Wo, const float* __restrict__ n1w){
    __shared__ float As[16][128];
    __shared__ float Bs[16][128];
    int tid = threadIdx.x, tx = tid & 15, ty = tid >> 4;
    int m0 = blockIdx.y*128, n0 = blockIdx.x*128;

    const float* ar[2]; float asc[2];
    const float* brp[2]; int brr[2];
    #pragma unroll
    for (int l = 0; l < 2; l++){
        int q = tid*2 + l;
        { int r = q >> 2; ar[l] = &Wv[(size_t)(m0+r)*HH + (q&3)*4]; asc[l] = n1w[m0+r]; }
        { int r = q >> 5; brp[l] = &Wo[(size_t)r*HH + n0 + (q&31)*4]; brr[l] = r; }
    }
    ull acc[8][4];
    #pragma unroll
    for (int i = 0; i < 8; i++)
        #pragma unroll
        for (int j = 0; j < 4; j++) acc[i][j] = 0ull;

    for (int k0 = 0; k0 < HH; k0 += 16){
        #pragma unroll
        for (int l = 0; l < 2; l++){
            int q = tid*2 + l; int r = q >> 2; int c = (q&3)*4;
            float4 v = *(const float4*)(ar[l] + k0);
            float s = asc[l];
            As[c+0][r] = v.x*s; As[c+1][r] = v.y*s; As[c+2][r] = v.z*s; As[c+3][r] = v.w*s;
        }
        #pragma unroll
        for (int l = 0; l < 2; l++){
            int q = tid*2 + l; int c = (q&31)*4;
            float4 v = *(const float4*)(brp[l] + (size_t)k0*HH);
            *(float4*)&Bs[brr[l]][c] = v;
        }
        __syncthreads();
        #pragma unroll
        for (int kk = 0; kk < 16; kk++){
            float a8[8];
            *(float4*)a8     = *(const float4*)&As[kk][ty*8];
            *(float4*)(a8+4) = *(const float4*)&As[kk][ty*8+4];
            ull b2[4];
            const ull* bp = (const ull*)&Bs[kk][tx*8];
            b2[0]=bp[0]; b2[1]=bp[1]; b2[2]=bp[2]; b2[3]=bp[3];
            #pragma unroll
            for (int i = 0; i < 8; i++){
                ull ap = pack2(a8[i]);
                #pragma unroll
                for (int j = 0; j < 4; j++) ffma2(acc[i][j], ap, b2[j]);
            }
        }
        __syncthreads();
    }
    #pragma unroll
    for (int i = 0; i < 8; i++){
        size_t ob = (size_t)(m0 + ty*8 + i)*HH + n0 + tx*8;
        #pragma unroll
        for (int jc = 0; jc < 4; jc++){
            float2 c2 = unpack2(acc[i][jc]);
            g_Wcomb[ob + jc*2 + 0] = c2.x;
            g_Wcomb[ob + jc*2 + 1] = c2.y;
        }
    }
}

// K5: res = x_sel + r1 * (x_sel @ Wcomb)   (M=nsel, N=K=2048), gathered A
__global__ __launch_bounds__(256,2) void k_attn(const float* __restrict__ x){
    int nsel = g_nsel;
    int m0 = blockIdx.y*128; if (m0 >= nsel) return;
    int n0 = blockIdx.x*128;
    __shared__ float As[16][128];
    __shared__ float Bs[16][128];
    int tid = threadIdx.x, tx = tid & 15, ty = tid >> 4;

    const float* ar[2];
    const float* brp[2]; int brr[2];
    #pragma unroll
    for (int l = 0; l < 2; l++){
        int q = tid*2 + l;
        { int r = q >> 2; int jj = m0 + r; int t = (jj < nsel) ? g_sel[jj] : g_sel[0];
          ar[l] = &x[(size_t)t*HH + (q&3)*4]; }
        { int r = q >> 5; brp[l] = &g_Wcomb[(size_t)r*HH + n0 + (q&31)*4]; brr[l] = r; }
    }
    ull acc[8][4];
    #pragma unroll
    for (int i = 0; i < 8; i++)
        #pragma unroll
        for (int j = 0; j < 4; j++) acc[i][j] = 0ull;

    for (int k0 = 0; k0 < HH; k0 += 16){
        #pragma unroll
        for (int l = 0; l < 2; l++){
            int q = tid*2 + l; int r = q >> 2; int c = (q&3)*4;
            float4 v = *(const float4*)(ar[l] + k0);
            As[c+0][r] = v.x; As[c+1][r] = v.y; As[c+2][r] = v.z; As[c+3][r] = v.w;
        }
        #pragma unroll
        for (int l = 0; l < 2; l++){
            int q = tid*2 + l; int c = (q&31)*4;
            float4 v = *(const float4*)(brp[l] + (size_t)k0*HH);
            *(float4*)&Bs[brr[l]][c] = v;
        }
        __syncthreads();
        #pragma unroll
        for (int kk = 0; kk < 16; kk++){
            float a8[8];
            *(float4*)a8     = *(const float4*)&As[kk][ty*8];
            *(float4*)(a8+4) = *(const float4*)&As[kk][ty*8+4];
            ull b2[4];
            const ull* bp = (const ull*)&Bs[kk][tx*8];
            b2[0]=bp[0]; b2[1]=bp[1]; b2[2]=bp[2]; b2[3]=bp[3];
            #pragma unroll
            for (int i = 0; i < 8; i++){
                ull ap = pack2(a8[i]);
                #pragma unroll
                for (int j = 0; j < 4; j++) ffma2(acc[i][j], ap, b2[j]);
            }
        }
        __syncthreads();
    }
    #pragma unroll
    for (int i = 0; i < 8; i++){
        int j = m0 + ty*8 + i; if (j >= nsel) continue;
        int t = g_sel[j];
        float r1v = g_r1[t];
        size_t ob = (size_t)j*HH + n0 + tx*8;
        size_t xb = (size_t)t*HH + n0 + tx*8;
        #pragma unroll
        for (int jc = 0; jc < 4; jc++){
            float2 c2 = unpack2(acc[i][jc]);
            g_res[ob + jc*2 + 0] = x[xb + jc*2 + 0] + r1v*c2.x;
            g_res[ob + jc*2 + 1] = x[xb + jc*2 + 1] + r1v*c2.y;
        }
    }
}

// rmsnorm2 scale for selected tokens
__global__ __launch_bounds__(256) void k_r2(){
    int j = blockIdx.x; if (j >= g_nsel) return;
    const float* r = &g_res[(size_t)j*HH];
    float ssq = 0.f;
    for (int i = threadIdx.x; i < HH; i += 256){ float v = r[i]; ssq += v*v; }
    __shared__ float sf[256];
    sf[threadIdx.x] = ssq; __syncthreads();
    for (int o = 128; o > 0; o >>= 1){
        if (threadIdx.x < o) sf[threadIdx.x] += sf[threadIdx.x+o];
        __syncthreads();
    }
    if (threadIdx.x == 0) g_r2[j] = rsqrtf(sf[0]*(1.f/HH) + EPS_F);
}

// K7: mode 0 -> hbuf = silu(r2*(res @ diag(n2w)*w_gate))
//     mode 1 -> hbuf *= r2*(res @ diag(n2w)*w_up)       (M=nsel, N=8192, K=2048)
__global__ __launch_bounds__(256,2) void k_mlp1(const float* __restrict__ Wb,
        const float* __restrict__ n2w, int mode){
    int nsel = g_nsel;
    int m0 = blockIdx.y*128; if (m0 >= nsel) return;
    int n0 = blockIdx.x*128;
    __shared__ float As[16][128];
    __shared__ float Bs[16][128];
    int tid = threadIdx.x, tx = tid & 15, ty = tid >> 4;

    const float* ar[2];
    const float* brp[2]; int brr[2];
    #pragma unroll
    for (int l = 0; l < 2; l++){
        int q = tid*2 + l;
        { int r = q >> 2; int jj = m0 + r; if (jj >= nsel) jj = 0;
          ar[l] = &g_res[(size_t)jj*HH + (q&3)*4]; }
        { int r = q >> 5; brp[l] = &Wb[(size_t)r*DFFC + n0 + (q&31)*4]; brr[l] = r; }
    }
    ull acc[8][4];
    #pragma unroll
    for (int i = 0; i < 8; i++)
        #pragma unroll
        for (int j = 0; j < 4; j++) acc[i][j] = 0ull;

    for (int k0 = 0; k0 < HH; k0 += 16){
        #pragma unroll
        for (int l = 0; l < 2; l++){
            int q = tid*2 + l; int r = q >> 2; int c = (q&3)*4;
            float4 v = *(const float4*)(ar[l] + k0);
            As[c+0][r] = v.x; As[c+1][r] = v.y; As[c+2][r] = v.z; As[c+3][r] = v.w;
        }
        #pragma unroll
        for (int l = 0; l < 2; l++){
            int q = tid*2 + l; int c = (q&31)*4;
            float sc = n2w[k0 + brr[l]];
            float4 v = *(const float4*)(brp[l] + (size_t)k0*DFFC);
            v.x *= sc; v.y *= sc; v.z *= sc; v.w *= sc;
            *(float4*)&Bs[brr[l]][c] = v;
        }
        __syncthreads();
        #pragma unroll
        for (int kk = 0; kk < 16; kk++){
            float a8[8];
            *(float4*)a8     = *(const float4*)&As[kk][ty*8];
            *(float4*)(a8+4) = *(const float4*)&As[kk][ty*8+4];
            ull b2[4];
            const ull* bp = (const ull*)&Bs[kk][tx*8];
            b2[0]=bp[0]; b2[1]=bp[1]; b2[2]=bp[2]; b2[3]=bp[3];
            #pragma unroll
            for (int i = 0; i < 8; i++){
                ull ap = pack2(a8[i]);
                #pragma unroll
                for (int j = 0; j < 4; j++) ffma2(acc[i][j], ap, b2[j]);
            }
        }
        __syncthreads();
    }
    #pragma unroll
    for (int i = 0; i < 8; i++){
        int j = m0 + ty*8 + i; if (j >= nsel) continue;
        float r2v = g_r2[j];
        size_t base = (size_t)j*DFFC + n0 + tx*8;
        #pragma unroll
        for (int jc = 0; jc < 4; jc++){
            float2 c2 = unpack2(acc[i][jc]);
            float z0 = r2v*c2.x, z1 = r2v*c2.y;
            if (mode == 0){
                g_hbuf[base + jc*2 + 0] = z0 / (1.f + expf(-z0));
                g_hbuf[base + jc*2 + 1] = z1 / (1.f + expf(-z1));
            } else {
                g_hbuf[base + jc*2 + 0] *= z0;
                g_hbuf[base + jc*2 + 1] *= z1;
            }
        }
    }
}

// K8: out[sel] = res + hbuf @ w_down    (M=nsel, N=2048, K=8192)
__global__ __launch_bounds__(256,2) void k_down(const float* __restrict__ Wd,
        float* __restrict__ out){
    int nsel = g_nsel;
    int m0 = blockIdx.y*128; if (m0 >= nsel) return;
    int n0 = blockIdx.x*128;
    __shared__ float As[16][128];
    __shared__ float Bs[16][128];
    int tid = threadIdx.x, tx = tid & 15, ty = tid >> 4;

    const float* ar[2];
    const float* brp[2]; int brr[2];
    #pragma unroll
    for (int l = 0; l < 2; l++){
        int q = tid*2 + l;
        { int r = q >> 2; int jj = m0 + r; if (jj >= nsel) jj = 0;
          ar[l] = &g_hbuf[(size_t)jj*DFFC + (q&3)*4]; }
        { int r = q >> 5; brp[l] = &Wd[(size_t)r*HH + n0 + (q&31)*4]; brr[l] = r; }
    }
    ull acc[8][4];
    #pragma unroll
    for (int i = 0; i < 8; i++)
        #pragma unroll
        for (int j = 0; j < 4; j++) acc[i][j] = 0ull;

    for (int k0 = 0; k0 < DFFC; k0 += 16){
        #pragma unroll
        for (int l = 0; l < 2; l++){
            int q = tid*2 + l; int r = q >> 2; int c = (q&3)*4;
            float4 v = *(const float4*)(ar[l] + k0);
            As[c+0][r] = v.x; As[c+1][r] = v.y; As[c+2][r] = v.z; As[c+3][r] = v.w;
        }
        #pragma unroll
        for (int l = 0; l < 2; l++){
            int q = tid*2 + l; int c = (q&31)*4;
            float4 v = *(const float4*)(brp[l] + (size_t)k0*HH);
            *(float4*)&Bs[brr[l]][c] = v;
        }
        __syncthreads();
        #pragma unroll
        for (int kk = 0; kk < 16; kk++){
            float a8[8];
            *(float4*)a8     = *(const float4*)&As[kk][ty*8];
            *(float4*)(a8+4) = *(const float4*)&As[kk][ty*8+4];
            ull b2[4];
            const ull* bp = (const ull*)&Bs[kk][tx*8];
            b2[0]=bp[0]; b2[1]=bp[1]; b2[2]=bp[2]; b2[3]=bp[3];
            #pragma unroll
            for (int i = 0; i < 8; i++){
                ull ap = pack2(a8[i]);
                #pragma unroll
                for (int j = 0; j < 4; j++) ffma2(acc[i][j], ap, b2[j]);
            }
        }
        __syncthreads();
    }
    #pragma unroll
    for (int i = 0; i < 8; i++){
        int j = m0 + ty*8 + i; if (j >= nsel) continue;
        int t = g_sel[j];
        size_t rb = (size_t)j*HH + n0 + tx*8;
        size_t ob = (size_t)t*HH + n0 + tx*8;
        #pragma unroll
        for (int jc = 0; jc < 4; jc++){
            float2 c2 = unpack2(acc[i][jc]);
            out[ob + jc*2 + 0] = g_res[rb + jc*2 + 0] + c2.x;
            out[ob + jc*2 + 1] = g_res[rb + jc*2 + 1] + c2.y;
        }
    }
}

// ---------------- launch ----------------------------------------------------
extern "C" void kernel_launch(void* const* d_in, const int* in_sizes, int n_in,
                              void* d_out, int out_size){
    const float* x   = (const float*)d_in[0];
    const float* wr  = (const float*)d_in[1];
    const float* br  = (const float*)d_in[2];
    // d_in[3] = Wq, d_in[4] = Wk : dead code (softmax over size-1 axis == 1)
    const float* Wv  = (const float*)d_in[5];
    const float* Wo  = (const float*)d_in[6];
    const float* wg  = (const float*)d_in[7];
    const float* wu  = (const float*)d_in[8];
    const float* wd  = (const float*)d_in[9];
    const float* n1w = (const float*)d_in[10];
    const float* n2w = (const float*)d_in[11];
    float* out = (float*)d_out;

    // default output: out = x (unmasked tokens pass through)
    cudaMemcpyAsync(out, x, (size_t)BSZ*HH*sizeof(float),
                    cudaMemcpyDeviceToDevice, 0);

    k_router <<<BSZ, 256>>>(x, wr, br);
    k_topk   <<<Bb, 1024>>>();
    k_zero   <<<1, 1>>>();
    k_compact<<<BSZ/256, 256>>>();

    k_wcomb  <<<dim3(16, 16),  256>>>(Wv, Wo, n1w);
    k_attn   <<<dim3(16, 128), 256>>>(x);
    k_r2     <<<BSZ, 256>>>();
    k_mlp1   <<<dim3(64, 128), 256>>>(wg, n2w, 0);
    k_mlp1   <<<dim3(64, 128), 256>>>(wu, n2w, 1);
    k_down   <<<dim3(16, 128), 256>>>(wd, out);
}

// round 4
// speedup vs baseline: 2.5239x; 2.5239x over previous
#include <cuda_runtime.h>
#include <math.h>
#include <stdint.h>

// Problem constants
#define Bb   4
#define SS   4096
#define HH   2048
#define DFFC 8192
#define BSZ  (Bb*SS)          // 16384 tokens
#define EPS_F 1e-5f

// ---------------- scratch (device globals; no allocation allowed) ----------
__device__ float g_logits[BSZ];
__device__ float g_r1[BSZ];
__device__ float g_thr[Bb];
__device__ int   g_sel[BSZ];
__device__ int   g_nsel;
__device__ float g_r2[BSZ];

__device__ float g_xr  [(size_t)BSZ*HH];     // x rounded to tf32
__device__ float g_wvr [(size_t)HH*HH];      // n1w[m]*Wv rounded      [m][k]
__device__ float g_woT [(size_t)HH*HH];      // Wo^T rounded           [n][k]
__device__ float g_WcT [(size_t)HH*HH];      // Wcomb^T rounded        [n][k]
__device__ float g_wgT [(size_t)DFFC*HH];    // (diag(n2w)*w_gate)^T   [n][k]
__device__ float g_wuT [(size_t)DFFC*HH];    // (diag(n2w)*w_up)^T     [n][k]
__device__ float g_wdT [(size_t)HH*DFFC];    // w_down^T rounded       [n][k]
__device__ float g_res [(size_t)BSZ*HH];     // residual fp32 (selected order)
__device__ float g_resr[(size_t)BSZ*HH];     // residual rounded tf32
__device__ float g_hbuf[(size_t)BSZ*DFFC];   // silu(gate) then h (tf32)

// ============================ PTX helpers ==================================
__device__ __forceinline__ uint32_t smem_to_u32(const void* p){
    uint32_t a;
    asm("{ .reg .u64 t; cvta.to.shared.u64 t, %1; cvt.u32.u64 %0, t; }" : "=r"(a) : "l"(p));
    return a;
}
__device__ __forceinline__ float to_tf32(float x){
    float r; asm("cvt.rna.tf32.f32 %0,%1;" : "=f"(r) : "f"(x)); return r;
}
__device__ __forceinline__ void cp16(uint32_t s, const void* g){
    asm volatile("cp.async.cg.shared.global [%0], [%1], 16;" :: "r"(s), "l"(g));
}
#define CP_COMMIT() asm volatile("cp.async.commit_group;" ::: "memory")
#define CP_WAIT1()  asm volatile("cp.async.wait_group 1;" ::: "memory")
#define CP_WAIT0()  asm volatile("cp.async.wait_group 0;" ::: "memory")

__device__ __forceinline__ void mma16n8k8(float* c, const uint32_t* a, const uint32_t* b){
    asm volatile("mma.sync.aligned.m16n8k8.row.col.f32.tf32.tf32.f32 "
        "{%0,%1,%2,%3},{%4,%5,%6,%7},{%8,%9},{%0,%1,%2,%3};"
        : "+f"(c[0]), "+f"(c[1]), "+f"(c[2]), "+f"(c[3])
        : "r"(a[0]), "r"(a[1]), "r"(a[2]), "r"(a[3]), "r"(b[0]), "r"(b[1]));
}

// ===================== GEMM mainloop (128x128, K-stage 16) =================
// 256 threads = 8 warps in 2x4 (m x n); warp tile 64x32; acc[4 mtile][4 ntile][4]
// SMEM: stage s: A at s*20480B, B at s*20480+10240B; rows padded to 20 floats.
#define TSTRIDE 20
#define STAGEB  20480
#define SMEM_BYTES (2*STAGEB)

__device__ __forceinline__ void gemm_ml(float (&acc)[4][4][4],
        const float* aP, const float* bP, int nK16,
        const float* smf, uint32_t sb, int tid)
{
    int lane = tid & 31;
    int mB = (tid >> 7) * 64;          // warp>>2
    int nB = ((tid >> 5) & 3) * 32;    // warp&3
    int row = tid >> 1, f8 = (tid & 1) * 8;
    uint32_t sA = sb + (row*TSTRIDE + f8)*4;
    uint32_t sB = sA + 10240;

    // prologue: stage 0
    cp16(sA,      aP);     cp16(sA + 16, aP + 4);
    cp16(sB,      bP);     cp16(sB + 16, bP + 4);
    CP_COMMIT();

    #pragma unroll 1
    for (int s = 0; s < nK16; s++){
        if (s + 1 < nK16){
            uint32_t off = ((s + 1) & 1) * STAGEB;
            const float* an = aP + (s + 1) * 16;
            const float* bn = bP + (s + 1) * 16;
            cp16(sA + off,      an);     cp16(sA + off + 16, an + 4);
            cp16(sB + off,      bn);     cp16(sB + off + 16, bn + 4);
            CP_COMMIT();
            CP_WAIT1();
        } else {
            CP_WAIT0();
        }
        __syncthreads();
        const uint32_t* As = (const uint32_t*)(smf + (s & 1)*(STAGEB/4));
        const uint32_t* Bs = As + 10240/4;
        #pragma unroll
        for (int ks = 0; ks < 16; ks += 8){
            uint32_t a[4][4], b[4][2];
            int c0 = ks + (lane & 3);
            #pragma unroll
            for (int i = 0; i < 4; i++){
                int r = mB + i*16 + (lane >> 2);
                a[i][0] = As[r*TSTRIDE + c0];
                a[i][1] = As[(r+8)*TSTRIDE + c0];
                a[i][2] = As[r*TSTRIDE + c0 + 4];
                a[i][3] = As[(r+8)*TSTRIDE + c0 + 4];
            }
            #pragma unroll
            for (int j = 0; j < 4; j++){
                int n = nB + j*8 + (lane >> 2);
                b[j][0] = Bs[n*TSTRIDE + c0];
                b[j][1] = Bs[n*TSTRIDE + c0 + 4];
            }
            #pragma unroll
            for (int i = 0; i < 4; i++)
                #pragma unroll
                for (int j = 0; j < 4; j++)
                    mma16n8k8(acc[i][j], a[i], b[j]);
        }
        __syncthreads();
    }
}

#define GEMM_PROLOG() \
    extern __shared__ float smf[]; \
    uint32_t sb = smem_to_u32(smf); \
    int tid = threadIdx.x; \
    int row = tid >> 1, f8 = (tid & 1) * 8; \
    float acc[4][4][4]; \
    _Pragma("unroll") for (int i = 0; i < 4; i++) \
    _Pragma("unroll") for (int j = 0; j < 4; j++) \
    _Pragma("unroll") for (int q = 0; q < 4; q++) acc[i][j][q] = 0.f;

#define EPI_VARS() \
    int lane = tid & 31; \
    int mB = (tid >> 7) * 64; \
    int nB = ((tid >> 5) & 3) * 32;

// =========================== small kernels =================================
__global__ __launch_bounds__(256) void k_router(const float* __restrict__ x,
        const float* __restrict__ wr, const float* __restrict__ br){
    int t = blockIdx.x;
    const float* xr = x + (size_t)t*HH;
    double ds = 0.0; float ssq = 0.f;
    for (int i = threadIdx.x; i < HH; i += 256){
        float v = xr[i];
        ds += (double)v * (double)wr[i];
        ssq += v*v;
    }
    __shared__ double sd[256];
    __shared__ float  sf[256];
    sd[threadIdx.x] = ds; sf[threadIdx.x] = ssq;
    __syncthreads();
    for (int o = 128; o > 0; o >>= 1){
        if (threadIdx.x < o){ sd[threadIdx.x] += sd[threadIdx.x+o]; sf[threadIdx.x] += sf[threadIdx.x+o]; }
        __syncthreads();
    }
    if (threadIdx.x == 0){
        g_logits[t] = (float)(sd[0] + (double)br[0]);
        g_r1[t]     = rsqrtf(sf[0]*(1.f/HH) + EPS_F);
    }
}

__global__ __launch_bounds__(1024) void k_topk(){
    __shared__ float s[SS];
    int b = blockIdx.x, tid = threadIdx.x;
    for (int i = tid; i < SS; i += 1024) s[i] = g_logits[b*SS + i];
    __syncthreads();
    for (int k = 2; k <= SS; k <<= 1){
        for (int j = k >> 1; j > 0; j >>= 1){
            for (int i = tid; i < SS; i += 1024){
                int ixj = i ^ j;
                if (ixj > i){
                    float a = s[i], c = s[ixj];
                    bool up = ((i & k) == 0);
                    if ((a > c) == up){ s[i] = c; s[ixj] = a; }
                }
            }
            __syncthreads();
        }
    }
    if (tid == 0) g_thr[b] = s[SS/2];
}

__global__ void k_zero(){ g_nsel = 0; }

__global__ __launch_bounds__(256) void k_compact(){
    int t = blockIdx.x*256 + threadIdx.x;
    if (t < BSZ && g_logits[t] >= g_thr[t/SS]){
        int p = atomicAdd(&g_nsel, 1);
        g_sel[p] = t;
    }
}

__global__ __launch_bounds__(256) void k_r2(){
    int j = blockIdx.x; if (j >= g_nsel) return;
    const float* r = &g_res[(size_t)j*HH];
    float ssq = 0.f;
    for (int i = threadIdx.x; i < HH; i += 256){ float v = r[i]; ssq += v*v; }
    __shared__ float sf[256];
    sf[threadIdx.x] = ssq; __syncthreads();
    for (int o = 128; o > 0; o >>= 1){
        if (threadIdx.x < o) sf[threadIdx.x] += sf[threadIdx.x+o];
        __syncthreads();
    }
    if (threadIdx.x == 0) g_r2[j] = rsqrtf(sf[0]*(1.f/HH) + EPS_F);
}

__global__ __launch_bounds__(256) void k_round(const float* __restrict__ in,
        float* __restrict__ out, int n4){
    int i = blockIdx.x*256 + threadIdx.x;
    if (i < n4){
        float4 v = ((const float4*)in)[i];
        v.x = to_tf32(v.x); v.y = to_tf32(v.y); v.z = to_tf32(v.z); v.w = to_tf32(v.w);
        ((float4*)out)[i] = v;
    }
}

__global__ __launch_bounds__(256) void k_scalewv(const float* __restrict__ Wv,
        const float* __restrict__ n1w){
    int i = blockIdx.x*256 + threadIdx.x;          // float4 index
    int row = i >> 9;                               // HH/4 = 512 per row
    float s = n1w[row];
    float4 v = ((const float4*)Wv)[i];
    v.x = to_tf32(v.x*s); v.y = to_tf32(v.y*s); v.z = to_tf32(v.z*s); v.w = to_tf32(v.w*s);
    ((float4*)g_wvr)[i] = v;
}

// transpose in[R][C] -> out[C][R], value tf32(in[r][c] * (scale? scale[r]:1))
__global__ __launch_bounds__(256) void k_transpose(const float* __restrict__ in,
        float* __restrict__ out, int R, int C, const float* __restrict__ scale){
    __shared__ float ts[32][33];
    int c0 = blockIdx.x*32, r0 = blockIdx.y*32;
    int tx = threadIdx.x, ty = threadIdx.y;       // 32 x 8
    #pragma unroll
    for (int i = 0; i < 32; i += 8){
        int r = r0 + ty + i;
        float v = in[(size_t)r*C + c0 + tx];
        if (scale) v *= scale[r];
        ts[ty+i][tx] = v;
    }
    __syncthreads();
    #pragma unroll
    for (int i = 0; i < 32; i += 8){
        int c = c0 + ty + i;
        out[(size_t)c*R + r0 + tx] = to_tf32(ts[tx][ty+i]);
    }
}

// ====================== mma.sync tf32 GEMM kernels =========================

// WcT[n][m] = sum_k Wo^T[n][k] * Wv'[m][k]   (A rows=woT, B rows=wvr)
__global__ __launch_bounds__(256) void tk_wcomb(){
    int y0 = blockIdx.y*128, x0 = blockIdx.x*128;
    GEMM_PROLOG();
    const float* aP = g_woT + (size_t)(y0+row)*HH + f8;
    const float* bP = g_wvr + (size_t)(x0+row)*HH + f8;
    gemm_ml(acc, aP, bP, HH/16, smf, sb, tid);
    EPI_VARS();
    #pragma unroll
    for (int i = 0; i < 4; i++)
        #pragma unroll
        for (int h = 0; h < 2; h++){
            int r = y0 + mB + i*16 + (lane>>2) + h*8;
            #pragma unroll
            for (int j = 0; j < 4; j++){
                int c = x0 + nB + j*8 + (lane&3)*2;
                g_WcT[(size_t)r*HH + c]     = to_tf32(acc[i][j][h*2]);
                g_WcT[(size_t)r*HH + c + 1] = to_tf32(acc[i][j][h*2+1]);
            }
        }
}

// res = x_sel + r1*(xr_sel @ Wcomb)   : A rows gathered tokens, B rows=WcT
__global__ __launch_bounds__(256) void tk_attn(const float* __restrict__ x){
    int nsel = g_nsel;
    int m0 = blockIdx.y*128; if (m0 >= nsel) return;
    int n0 = blockIdx.x*128;
    GEMM_PROLOG();
    int ja = m0 + row; if (ja >= nsel) ja = nsel - 1;
    const float* aP = g_xr  + (size_t)g_sel[ja]*HH + f8;
    const float* bP = g_WcT + (size_t)(n0+row)*HH + f8;
    gemm_ml(acc, aP, bP, HH/16, smf, sb, tid);
    EPI_VARS();
    #pragma unroll
    for (int i = 0; i < 4; i++)
        #pragma unroll
        for (int h = 0; h < 2; h++){
            int j = m0 + mB + i*16 + (lane>>2) + h*8;
            if (j >= nsel) continue;
            int tok = g_sel[j];
            float r1v = g_r1[tok];
            #pragma unroll
            for (int jj = 0; jj < 4; jj++){
                int c = n0 + nB + jj*8 + (lane&3)*2;
                size_t ob = (size_t)j*HH + c, xb = (size_t)tok*HH + c;
                float v0 = x[xb]   + r1v*acc[i][jj][h*2];
                float v1 = x[xb+1] + r1v*acc[i][jj][h*2+1];
                g_res[ob]   = v0;  g_res[ob+1]  = v1;
                g_resr[ob]  = to_tf32(v0);
                g_resr[ob+1]= to_tf32(v1);
            }
        }
}

// gate: g_hbuf = silu(r2 * (resr @ wgT'))
__global__ __launch_bounds__(256) void tk_gate(){
    int nsel = g_nsel;
    int m0 = blockIdx.y*128; if (m0 >= nsel) return;
    int n0 = blockIdx.x*128;
    GEMM_PROLOG();
    int ja = m0 + row; if (ja >= nsel) ja = nsel - 1;
    const float* aP = g_resr + (size_t)ja*HH + f8;
    const float* bP = g_wgT  + (size_t)(n0+row)*HH + f8;
    gemm_ml(acc, aP, bP, HH/16, smf, sb, tid);
    EPI_VARS();
    #pragma unroll
    for (int i = 0; i < 4; i++)
        #pragma unroll
        for (int h = 0; h < 2; h++){
            int j = m0 + mB + i*16 + (lane>>2) + h*8;
            if (j >= nsel) continue;
            float r2v = g_r2[j];
            #pragma unroll
            for (int jj = 0; jj < 4; jj++){
                int c = n0 + nB + jj*8 + (lane&3)*2;
                size_t ob = (size_t)j*DFFC + c;
                float z0 = r2v*acc[i][jj][h*2];
                float z1 = r2v*acc[i][jj][h*2+1];
                g_hbuf[ob]   = z0 / (1.f + expf(-z0));
                g_hbuf[ob+1] = z1 / (1.f + expf(-z1));
            }
        }
}

// up + combine: g_hbuf = tf32( g_hbuf * (r2 * (resr @ wuT')) )
__global__ __launch_bounds__(256) void tk_up(){
    int nsel = g_nsel;
    int m0 = blockIdx.y*128; if (m0 >= nsel) return;
    int n0 = blockIdx.x*128;
    GEMM_PROLOG();
    int ja = m0 + row; if (ja >= nsel) ja = nsel - 1;
    const float* aP = g_resr + (size_t)ja*HH + f8;
    const float* bP = g_wuT  + (size_t)(n0+row)*HH + f8;
    gemm_ml(acc, aP, bP, HH/16, smf, sb, tid);
    EPI_VARS();
    #pragma unroll
    for (int i = 0; i < 4; i++)
        #pragma unroll
        for (int h = 0; h < 2; h++){
            int j = m0 + mB + i*16 + (lane>>2) + h*8;
            if (j >= nsel) continue;
            float r2v = g_r2[j];
            #pragma unroll
            for (int jj = 0; jj < 4; jj++){
                int c = n0 + nB + jj*8 + (lane&3)*2;
                size_t ob = (size_t)j*DFFC + c;
                float z0 = r2v*acc[i][jj][h*2];
                float z1 = r2v*acc[i][jj][h*2+1];
                g_hbuf[ob]   = to_tf32(g_hbuf[ob]   * z0);
                g_hbuf[ob+1] = to_tf32(g_hbuf[ob+1] * z1);
            }
        }
}

// out[sel] = res + hbuf @ wdT'   (K = 8192)
__global__ __launch_bounds__(256) void tk_down(float* __restrict__ out){
    int nsel = g_nsel;
    int m0 = blockIdx.y*128; if (m0 >= nsel) return;
    int n0 = blockIdx.x*128;
    GEMM_PROLOG();
    int ja = m0 + row; if (ja >= nsel) ja = nsel - 1;
    const float* aP = g_hbuf + (size_t)ja*DFFC + f8;
    const float* bP = g_wdT  + (size_t)(n0+row)*DFFC + f8;
    gemm_ml(acc, aP, bP, DFFC/16, smf, sb, tid);
    EPI_VARS();
    #pragma unroll
    for (int i = 0; i < 4; i++)
        #pragma unroll
        for (int h = 0; h < 2; h++){
            int j = m0 + mB + i*16 + (lane>>2) + h*8;
            if (j >= nsel) continue;
            int tok = g_sel[j];
            #pragma unroll
            for (int jj = 0; jj < 4; jj++){
                int c = n0 + nB + jj*8 + (lane&3)*2;
                size_t rb = (size_t)j*HH + c, ob = (size_t)tok*HH + c;
                out[ob]   = g_res[rb]   + acc[i][jj][h*2];
                out[ob+1] = g_res[rb+1] + acc[i][jj][h*2+1];
            }
        }
}

// ---------------- launch ----------------------------------------------------
extern "C" void kernel_launch(void* const* d_in, const int* in_sizes, int n_in,
                              void* d_out, int out_size){
    const float* x   = (const float*)d_in[0];
    const float* wr  = (const float*)d_in[1];
    const float* br  = (const float*)d_in[2];
    // d_in[3] = Wq, d_in[4] = Wk : dead (softmax over size-1 axis == 1)
    const float* Wv  = (const float*)d_in[5];
    const float* Wo  = (const float*)d_in[6];
    const float* wg  = (const float*)d_in[7];
    const float* wu  = (const float*)d_in[8];
    const float* wd  = (const float*)d_in[9];
    const float* n1w = (const float*)d_in[10];
    const float* n2w = (const float*)d_in[11];
    float* out = (float*)d_out;

    // default output: pass-through tokens
    cudaMemcpyAsync(out, x, (size_t)BSZ*HH*sizeof(float), cudaMemcpyDeviceToDevice, 0);

    k_router <<<BSZ, 256>>>(x, wr, br);
    k_topk   <<<Bb, 1024>>>();
    k_zero   <<<1, 1>>>();
    k_compact<<<BSZ/256, 256>>>();

    // prep: rounded / transposed operands
    float* xr_p; cudaGetSymbolAddress((void**)&xr_p, g_xr);
    k_round    <<<(BSZ*HH/4 + 255)/256, 256>>>(x, xr_p, BSZ*HH/4);
    k_scalewv  <<<(HH*HH/4)/256, 256>>>(Wv, n1w);
    float* woT_p; cudaGetSymbolAddress((void**)&woT_p, g_woT);
    float* wgT_p; cudaGetSymbolAddress((void**)&wgT_p, g_wgT);
    float* wuT_p; cudaGetSymbolAddress((void**)&wuT_p, g_wuT);
    float* wdT_p; cudaGetSymbolAddress((void**)&wdT_p, g_wdT);
    k_transpose<<<dim3(HH/32,  HH/32),   dim3(32,8)>>>(Wo, woT_p, HH,  HH,  nullptr);
    k_transpose<<<dim3(DFFC/32,HH/32),   dim3(32,8)>>>(wg, wgT_p, HH,  DFFC, n2w);
    k_transpose<<<dim3(DFFC/32,HH/32),   dim3(32,8)>>>(wu, wuT_p, HH,  DFFC, n2w);
    k_transpose<<<dim3(HH/32,  DFFC/32), dim3(32,8)>>>(wd, wdT_p, DFFC, HH,  nullptr);

    tk_wcomb<<<dim3(16, 16),  256, SMEM_BYTES>>>();
    tk_attn <<<dim3(16, 128), 256, SMEM_BYTES>>>(x);
    k_r2    <<<BSZ, 256>>>();
    tk_gate <<<dim3(64, 128), 256, SMEM_BYTES>>>();
    tk_up   <<<dim3(64, 128), 256, SMEM_BYTES>>>();
    tk_down <<<dim3(16, 128), 256, SMEM_BYTES>>>(out);
}

// round 5
// speedup vs baseline: 2.5287x; 1.0019x over previous
#include <cuda_runtime.h>
#include <math.h>
#include <stdint.h>

// Problem constants
#define Bb   4
#define SS   4096
#define HH   2048
#define DFFC 8192
#define BSZ  (Bb*SS)          // 16384 tokens
#define EPS_F 1e-5f

// ---------------- scratch (device globals; no allocation allowed) ----------
__device__ float g_logits[BSZ];
__device__ float g_r1[BSZ];
__device__ float g_thr[Bb];
__device__ int   g_sel[BSZ];
__device__ int   g_nsel;
__device__ float g_r2[BSZ];

__device__ float g_xr  [(size_t)BSZ*HH];     // x rounded to tf32
__device__ float g_wvr [(size_t)HH*HH];      // n1w[m]*Wv rounded      [m][k]
__device__ float g_woT [(size_t)HH*HH];      // Wo^T rounded           [n][k]
__device__ float g_WcT [(size_t)HH*HH];      // Wcomb^T rounded        [n][k]
__device__ float g_wgT [(size_t)DFFC*HH];    // (diag(n2w)*w_gate)^T   [n][k]
__device__ float g_wuT [(size_t)DFFC*HH];    // (diag(n2w)*w_up)^T     [n][k]
__device__ float g_wdT [(size_t)HH*DFFC];    // w_down^T rounded       [n][k]
__device__ float g_res [(size_t)BSZ*HH];     // residual fp32 (selected order)
__device__ float g_resr[(size_t)BSZ*HH];     // residual rounded tf32
__device__ float g_hbuf[(size_t)BSZ*DFFC];   // silu(gate) then h (tf32)

// ============================ PTX helpers ==================================
__device__ __forceinline__ uint32_t smem_to_u32(const void* p){
    uint32_t a;
    asm("{ .reg .u64 t; cvta.to.shared.u64 t, %1; cvt.u32.u64 %0, t; }" : "=r"(a) : "l"(p));
    return a;
}
__device__ __forceinline__ float to_tf32(float x){
    float r; asm("cvt.rna.tf32.f32 %0,%1;" : "=f"(r) : "f"(x)); return r;
}
__device__ __forceinline__ void cp16(uint32_t s, const void* g){
    asm volatile("cp.async.cg.shared.global [%0], [%1], 16;" :: "r"(s), "l"(g));
}
#define CP_COMMIT() asm volatile("cp.async.commit_group;" ::: "memory")
#define CP_WAIT1()  asm volatile("cp.async.wait_group 1;" ::: "memory")
#define CP_WAIT0()  asm volatile("cp.async.wait_group 0;" ::: "memory")

__device__ __forceinline__ void mma16n8k8(float* c, const uint32_t* a, const uint32_t* b){
    asm volatile("mma.sync.aligned.m16n8k8.row.col.f32.tf32.tf32.f32 "
        "{%0,%1,%2,%3},{%4,%5,%6,%7},{%8,%9},{%0,%1,%2,%3};"
        : "+f"(c[0]), "+f"(c[1]), "+f"(c[2]), "+f"(c[3])
        : "r"(a[0]), "r"(a[1]), "r"(a[2]), "r"(a[3]), "r"(b[0]), "r"(b[1]));
}

// ===================== GEMM mainloop (128x128, K-stage 16) =================
// 256 threads = 8 warps in 2x4 (m x n); warp tile 64x32; acc[4 mtile][4 ntile][4]
// SMEM: stage s: A at s*20480B, B at s*20480+10240B; rows padded to 20 floats.
#define TSTRIDE 20
#define STAGEB  20480
#define SMEM_BYTES (2*STAGEB)

__device__ __forceinline__ void gemm_ml(float (&acc)[4][4][4],
        const float* aP, const float* bP, int nK16,
        const float* smf, uint32_t sb, int tid)
{
    int lane = tid & 31;
    int mB = (tid >> 7) * 64;          // warp>>2
    int nB = ((tid >> 5) & 3) * 32;    // warp&3
    int row = tid >> 1, f8 = (tid & 1) * 8;
    uint32_t sA = sb + (row*TSTRIDE + f8)*4;
    uint32_t sB = sA + 10240;

    // prologue: stage 0
    cp16(sA,      aP);     cp16(sA + 16, aP + 4);
    cp16(sB,      bP);     cp16(sB + 16, bP + 4);
    CP_COMMIT();

    #pragma unroll 1
    for (int s = 0; s < nK16; s++){
        if (s + 1 < nK16){
            uint32_t off = ((s + 1) & 1) * STAGEB;
            const float* an = aP + (s + 1) * 16;
            const float* bn = bP + (s + 1) * 16;
            cp16(sA + off,      an);     cp16(sA + off + 16, an + 4);
            cp16(sB + off,      bn);     cp16(sB + off + 16, bn + 4);
            CP_COMMIT();
            CP_WAIT1();
        } else {
            CP_WAIT0();
        }
        __syncthreads();
        const uint32_t* As = (const uint32_t*)(smf + (s & 1)*(STAGEB/4));
        const uint32_t* Bs = As + 10240/4;
        #pragma unroll
        for (int ks = 0; ks < 16; ks += 8){
            uint32_t a[4][4], b[4][2];
            int c0 = ks + (lane & 3);
            #pragma unroll
            for (int i = 0; i < 4; i++){
                int r = mB + i*16 + (lane >> 2);
                a[i][0] = As[r*TSTRIDE + c0];
                a[i][1] = As[(r+8)*TSTRIDE + c0];
                a[i][2] = As[r*TSTRIDE + c0 + 4];
                a[i][3] = As[(r+8)*TSTRIDE + c0 + 4];
            }
            #pragma unroll
            for (int j = 0; j < 4; j++){
                int n = nB + j*8 + (lane >> 2);
                b[j][0] = Bs[n*TSTRIDE + c0];
                b[j][1] = Bs[n*TSTRIDE + c0 + 4];
            }
            #pragma unroll
            for (int i = 0; i < 4; i++)
                #pragma unroll
                for (int j = 0; j < 4; j++)
                    mma16n8k8(acc[i][j], a[i], b[j]);
        }
        __syncthreads();
    }
}

#define GEMM_PROLOG() \
    extern __shared__ float smf[]; \
    uint32_t sb = smem_to_u32(smf); \
    int tid = threadIdx.x; \
    int row = tid >> 1, f8 = (tid & 1) * 8; \
    float acc[4][4][4]; \
    _Pragma("unroll") for (int i = 0; i < 4; i++) \
    _Pragma("unroll") for (int j = 0; j < 4; j++) \
    _Pragma("unroll") for (int q = 0; q < 4; q++) acc[i][j][q] = 0.f;

#define EPI_VARS() \
    int lane = tid & 31; \
    int mB = (tid >> 7) * 64; \
    int nB = ((tid >> 5) & 3) * 32;

// =========================== small kernels =================================
__global__ __launch_bounds__(256) void k_router(const float* __restrict__ x,
        const float* __restrict__ wr, const float* __restrict__ br){
    int t = blockIdx.x;
    const float* xr = x + (size_t)t*HH;
    double ds = 0.0; float ssq = 0.f;
    for (int i = threadIdx.x; i < HH; i += 256){
        float v = xr[i];
        ds += (double)v * (double)wr[i];
        ssq += v*v;
    }
    __shared__ double sd[256];
    __shared__ float  sf[256];
    sd[threadIdx.x] = ds; sf[threadIdx.x] = ssq;
    __syncthreads();
    for (int o = 128; o > 0; o >>= 1){
        if (threadIdx.x < o){ sd[threadIdx.x] += sd[threadIdx.x+o]; sf[threadIdx.x] += sf[threadIdx.x+o]; }
        __syncthreads();
    }
    if (threadIdx.x == 0){
        g_logits[t] = (float)(sd[0] + (double)br[0]);
        g_r1[t]     = rsqrtf(sf[0]*(1.f/HH) + EPS_F);
    }
}

__global__ __launch_bounds__(1024) void k_topk(){
    __shared__ float s[SS];
    int b = blockIdx.x, tid = threadIdx.x;
    for (int i = tid; i < SS; i += 1024) s[i] = g_logits[b*SS + i];
    __syncthreads();
    for (int k = 2; k <= SS; k <<= 1){
        for (int j = k >> 1; j > 0; j >>= 1){
            for (int i = tid; i < SS; i += 1024){
                int ixj = i ^ j;
                if (ixj > i){
                    float a = s[i], c = s[ixj];
                    bool up = ((i & k) == 0);
                    if ((a > c) == up){ s[i] = c; s[ixj] = a; }
                }
            }
            __syncthreads();
        }
    }
    if (tid == 0) g_thr[b] = s[SS/2];
}

__global__ void k_zero(){ g_nsel = 0; }

__global__ __launch_bounds__(256) void k_compact(){
    int t = blockIdx.x*256 + threadIdx.x;
    if (t < BSZ && g_logits[t] >= g_thr[t/SS]){
        int p = atomicAdd(&g_nsel, 1);
        g_sel[p] = t;
    }
}

__global__ __launch_bounds__(256) void k_r2(){
    int j = blockIdx.x; if (j >= g_nsel) return;
    const float* r = &g_res[(size_t)j*HH];
    float ssq = 0.f;
    for (int i = threadIdx.x; i < HH; i += 256){ float v = r[i]; ssq += v*v; }
    __shared__ float sf[256];
    sf[threadIdx.x] = ssq; __syncthreads();
    for (int o = 128; o > 0; o >>= 1){
        if (threadIdx.x < o) sf[threadIdx.x] += sf[threadIdx.x+o];
        __syncthreads();
    }
    if (threadIdx.x == 0) g_r2[j] = rsqrtf(sf[0]*(1.f/HH) + EPS_F);
}

__global__ __launch_bounds__(256) void k_round(const float* __restrict__ in,
        float* __restrict__ out, int n4){
    int i = blockIdx.x*256 + threadIdx.x;
    if (i < n4){
        float4 v = ((const float4*)in)[i];
        v.x = to_tf32(v.x); v.y = to_tf32(v.y); v.z = to_tf32(v.z); v.w = to_tf32(v.w);
        ((float4*)out)[i] = v;
    }
}

__global__ __launch_bounds__(256) void k_scalewv(const float* __restrict__ Wv,
        const float* __restrict__ n1w){
    int i = blockIdx.x*256 + threadIdx.x;          // float4 index
    int row = i >> 9;                               // HH/4 = 512 per row
    float s = n1w[row];
    float4 v = ((const float4*)Wv)[i];
    v.x = to_tf32(v.x*s); v.y = to_tf32(v.y*s); v.z = to_tf32(v.z*s); v.w = to_tf32(v.w*s);
    ((float4*)g_wvr)[i] = v;
}

// transpose in[R][C] -> out[C][R], value tf32(in[r][c] * (scale? scale[r]:1))
__global__ __launch_bounds__(256) void k_transpose(const float* __restrict__ in,
        float* __restrict__ out, int R, int C, const float* __restrict__ scale){
    __shared__ float ts[32][33];
    int c0 = blockIdx.x*32, r0 = blockIdx.y*32;
    int tx = threadIdx.x, ty = threadIdx.y;       // 32 x 8
    #pragma unroll
    for (int i = 0; i < 32; i += 8){
        int r = r0 + ty + i;
        float v = in[(size_t)r*C + c0 + tx];
        if (scale) v *= scale[r];
        ts[ty+i][tx] = v;
    }
    __syncthreads();
    #pragma unroll
    for (int i = 0; i < 32; i += 8){
        int c = c0 + ty + i;
        out[(size_t)c*R + r0 + tx] = to_tf32(ts[tx][ty+i]);
    }
}

// ====================== mma.sync tf32 GEMM kernels =========================

// WcT[n][m] = sum_k Wo^T[n][k] * Wv'[m][k]   (A rows=woT, B rows=wvr)
__global__ __launch_bounds__(256) void tk_wcomb(){
    int y0 = blockIdx.y*128, x0 = blockIdx.x*128;
    GEMM_PROLOG();
    const float* aP = g_woT + (size_t)(y0+row)*HH + f8;
    const float* bP = g_wvr + (size_t)(x0+row)*HH + f8;
    gemm_ml(acc, aP, bP, HH/16, smf, sb, tid);
    EPI_VARS();
    #pragma unroll
    for (int i = 0; i < 4; i++)
        #pragma unroll
        for (int h = 0; h < 2; h++){
            int r = y0 + mB + i*16 + (lane>>2) + h*8;
            #pragma unroll
            for (int j = 0; j < 4; j++){
                int c = x0 + nB + j*8 + (lane&3)*2;
                g_WcT[(size_t)r*HH + c]     = to_tf32(acc[i][j][h*2]);
                g_WcT[(size_t)r*HH + c + 1] = to_tf32(acc[i][j][h*2+1]);
            }
        }
}

// res = x_sel + r1*(xr_sel @ Wcomb)   : A rows gathered tokens, B rows=WcT
__global__ __launch_bounds__(256) void tk_attn(const float* __restrict__ x){
    int nsel = g_nsel;
    int m0 = blockIdx.y*128; if (m0 >= nsel) return;
    int n0 = blockIdx.x*128;
    GEMM_PROLOG();
    int ja = m0 + row; if (ja >= nsel) ja = nsel - 1;
    const float* aP = g_xr  + (size_t)g_sel[ja]*HH + f8;
    const float* bP = g_WcT + (size_t)(n0+row)*HH + f8;
    gemm_ml(acc, aP, bP, HH/16, smf, sb, tid);
    EPI_VARS();
    #pragma unroll
    for (int i = 0; i < 4; i++)
        #pragma unroll
        for (int h = 0; h < 2; h++){
            int j = m0 + mB + i*16 + (lane>>2) + h*8;
            if (j >= nsel) continue;
            int tok = g_sel[j];
            float r1v = g_r1[tok];
            #pragma unroll
            for (int jj = 0; jj < 4; jj++){
                int c = n0 + nB + jj*8 + (lane&3)*2;
                size_t ob = (size_t)j*HH + c, xb = (size_t)tok*HH + c;
                float v0 = x[xb]   + r1v*acc[i][jj][h*2];
                float v1 = x[xb+1] + r1v*acc[i][jj][h*2+1];
                g_res[ob]   = v0;  g_res[ob+1]  = v1;
                g_resr[ob]  = to_tf32(v0);
                g_resr[ob+1]= to_tf32(v1);
            }
        }
}

// gate: g_hbuf = silu(r2 * (resr @ wgT'))
__global__ __launch_bounds__(256) void tk_gate(){
    int nsel = g_nsel;
    int m0 = blockIdx.y*128; if (m0 >= nsel) return;
    int n0 = blockIdx.x*128;
    GEMM_PROLOG();
    int ja = m0 + row; if (ja >= nsel) ja = nsel - 1;
    const float* aP = g_resr + (size_t)ja*HH + f8;
    const float* bP = g_wgT  + (size_t)(n0+row)*HH + f8;
    gemm_ml(acc, aP, bP, HH/16, smf, sb, tid);
    EPI_VARS();
    #pragma unroll
    for (int i = 0; i < 4; i++)
        #pragma unroll
        for (int h = 0; h < 2; h++){
            int j = m0 + mB + i*16 + (lane>>2) + h*8;
            if (j >= nsel) continue;
            float r2v = g_r2[j];
            #pragma unroll
            for (int jj = 0; jj < 4; jj++){
                int c = n0 + nB + jj*8 + (lane&3)*2;
                size_t ob = (size_t)j*DFFC + c;
                float z0 = r2v*acc[i][jj][h*2];
                float z1 = r2v*acc[i][jj][h*2+1];
                g_hbuf[ob]   = z0 / (1.f + expf(-z0));
                g_hbuf[ob+1] = z1 / (1.f + expf(-z1));
            }
        }
}

// up + combine: g_hbuf = tf32( g_hbuf * (r2 * (resr @ wuT')) )
__global__ __launch_bounds__(256) void tk_up(){
    int nsel = g_nsel;
    int m0 = blockIdx.y*128; if (m0 >= nsel) return;
    int n0 = blockIdx.x*128;
    GEMM_PROLOG();
    int ja = m0 + row; if (ja >= nsel) ja = nsel - 1;
    const float* aP = g_resr + (size_t)ja*HH + f8;
    const float* bP = g_wuT  + (size_t)(n0+row)*HH + f8;
    gemm_ml(acc, aP, bP, HH/16, smf, sb, tid);
    EPI_VARS();
    #pragma unroll
    for (int i = 0; i < 4; i++)
        #pragma unroll
        for (int h = 0; h < 2; h++){
            int j = m0 + mB + i*16 + (lane>>2) + h*8;
            if (j >= nsel) continue;
            float r2v = g_r2[j];
            #pragma unroll
            for (int jj = 0; jj < 4; jj++){
                int c = n0 + nB + jj*8 + (lane&3)*2;
                size_t ob = (size_t)j*DFFC + c;
                float z0 = r2v*acc[i][jj][h*2];
                float z1 = r2v*acc[i][jj][h*2+1];
                g_hbuf[ob]   = to_tf32(g_hbuf[ob]   * z0);
                g_hbuf[ob+1] = to_tf32(g_hbuf[ob+1] * z1);
            }
        }
}

// out[sel] = res + hbuf @ wdT'   (K = 8192)
__global__ __launch_bounds__(256) void tk_down(float* __restrict__ out){
    int nsel = g_nsel;
    int m0 = blockIdx.y*128; if (m0 >= nsel) return;
    int n0 = blockIdx.x*128;
    GEMM_PROLOG();
    int ja = m0 + row; if (ja >= nsel) ja = nsel - 1;
    const float* aP = g_hbuf + (size_t)ja*DFFC + f8;
    const float* bP = g_wdT  + (size_t)(n0+row)*DFFC + f8;
    gemm_ml(acc, aP, bP, DFFC/16, smf, sb, tid);
    EPI_VARS();
    #pragma unroll
    for (int i = 0; i < 4; i++)
        #pragma unroll
        for (int h = 0; h < 2; h++){
            int j = m0 + mB + i*16 + (lane>>2) + h*8;
            if (j >= nsel) continue;
            int tok = g_sel[j];
            #pragma unroll
            for (int jj = 0; jj < 4; jj++){
                int c = n0 + nB + jj*8 + (lane&3)*2;
                size_t rb = (size_t)j*HH + c, ob = (size_t)tok*HH + c;
                out[ob]   = g_res[rb]   + acc[i][jj][h*2];
                out[ob+1] = g_res[rb+1] + acc[i][jj][h*2+1];
            }
        }
}

// ---------------- launch ----------------------------------------------------
extern "C" void kernel_launch(void* const* d_in, const int* in_sizes, int n_in,
                              void* d_out, int out_size){
    const float* x   = (const float*)d_in[0];
    const float* wr  = (const float*)d_in[1];
    const float* br  = (const float*)d_in[2];
    // d_in[3] = Wq, d_in[4] = Wk : dead (softmax over size-1 axis == 1)
    const float* Wv  = (const float*)d_in[5];
    const float* Wo  = (const float*)d_in[6];
    const float* wg  = (const float*)d_in[7];
    const float* wu  = (const float*)d_in[8];
    const float* wd  = (const float*)d_in[9];
    const float* n1w = (const float*)d_in[10];
    const float* n2w = (const float*)d_in[11];
    float* out = (float*)d_out;

    // default output: pass-through tokens
    cudaMemcpyAsync(out, x, (size_t)BSZ*HH*sizeof(float), cudaMemcpyDeviceToDevice, 0);

    k_router <<<BSZ, 256>>>(x, wr, br);
    k_topk   <<<Bb, 1024>>>();
    k_zero   <<<1, 1>>>();
    k_compact<<<BSZ/256, 256>>>();

    // prep: rounded / transposed operands
    float* xr_p; cudaGetSymbolAddress((void**)&xr_p, g_xr);
    k_round    <<<(BSZ*HH/4 + 255)/256, 256>>>(x, xr_p, BSZ*HH/4);
    k_scalewv  <<<(HH*HH/4)/256, 256>>>(Wv, n1w);
    float* woT_p; cudaGetSymbolAddress((void**)&woT_p, g_woT);
    float* wgT_p; cudaGetSymbolAddress((void**)&wgT_p, g_wgT);
    float* wuT_p; cudaGetSymbolAddress((void**)&wuT_p, g_wuT);
    float* wdT_p; cudaGetSymbolAddress((void**)&wdT_p, g_wdT);
    k_transpose<<<dim3(HH/32,  HH/32),   dim3(32,8)>>>(Wo, woT_p, HH,  HH,  nullptr);
    k_transpose<<<dim3(DFFC/32,HH/32),   dim3(32,8)>>>(wg, wgT_p, HH,  DFFC, n2w);
    k_transpose<<<dim3(DFFC/32,HH/32),   dim3(32,8)>>>(wu, wuT_p, HH,  DFFC, n2w);
    k_transpose<<<dim3(HH/32,  DFFC/32), dim3(32,8)>>>(wd, wdT_p, DFFC, HH,  nullptr);

    tk_wcomb<<<dim3(16, 16),  256, SMEM_BYTES>>>();
    tk_attn <<<dim3(16, 128), 256, SMEM_BYTES>>>(x);
    k_r2    <<<BSZ, 256>>>();
    tk_gate <<<dim3(64, 128), 256, SMEM_BYTES>>>();
    tk_up   <<<dim3(64, 128), 256, SMEM_BYTES>>>();
    tk_down <<<dim3(16, 128), 256, SMEM_BYTES>>>(out);
}

// round 6
// speedup vs baseline: 2.5288x; 1.0000x over previous
#include <cuda_runtime.h>
#include <math.h>
#include <stdint.h>

// Problem constants
#define Bb   4
#define SS   4096
#define HH   2048
#define DFFC 8192
#define BSZ  (Bb*SS)          // 16384 tokens
#define EPS_F 1e-5f

// ---------------- scratch (device globals; no allocation allowed) ----------
__device__ float g_logits[BSZ];
__device__ float g_r1[BSZ];
__device__ float g_thr[Bb];
__device__ int   g_sel[BSZ];
__device__ int   g_nsel;
__device__ float g_r2[BSZ];

__device__ float g_xr  [(size_t)BSZ*HH];     // x rounded to tf32
__device__ float g_wvr [(size_t)HH*HH];      // n1w[m]*Wv rounded      [m][k]
__device__ float g_woT [(size_t)HH*HH];      // Wo^T rounded           [n][k]
__device__ float g_WcT [(size_t)HH*HH];      // Wcomb^T rounded        [n][k]
__device__ float g_wgT [(size_t)DFFC*HH];    // (diag(n2w)*w_gate)^T   [n][k]
__device__ float g_wuT [(size_t)DFFC*HH];    // (diag(n2w)*w_up)^T     [n][k]
__device__ float g_wdT [(size_t)HH*DFFC];    // w_down^T rounded       [n][k]
__device__ float g_res [(size_t)BSZ*HH];     // residual fp32 (selected order)
__device__ float g_resr[(size_t)BSZ*HH];     // residual rounded tf32
__device__ float g_hbuf[(size_t)BSZ*DFFC];   // silu(gate) then h (tf32)

// ============================ PTX helpers ==================================
__device__ __forceinline__ uint32_t smem_to_u32(const void* p){
    uint32_t a;
    asm("{ .reg .u64 t; cvta.to.shared.u64 t, %1; cvt.u32.u64 %0, t; }" : "=r"(a) : "l"(p));
    return a;
}
__device__ __forceinline__ float to_tf32(float x){
    float r; asm("cvt.rna.tf32.f32 %0,%1;" : "=f"(r) : "f"(x)); return r;
}
__device__ __forceinline__ void cp16(uint32_t s, const void* g){
    asm volatile("cp.async.cg.shared.global [%0], [%1], 16;" :: "r"(s), "l"(g));
}
#define CP_COMMIT() asm volatile("cp.async.commit_group;" ::: "memory")
#define CP_WAIT1()  asm volatile("cp.async.wait_group 1;" ::: "memory")
#define CP_WAIT0()  asm volatile("cp.async.wait_group 0;" ::: "memory")

__device__ __forceinline__ void mma16n8k8(float* c, const uint32_t* a, const uint32_t* b){
    asm volatile("mma.sync.aligned.m16n8k8.row.col.f32.tf32.tf32.f32 "
        "{%0,%1,%2,%3},{%4,%5,%6,%7},{%8,%9},{%0,%1,%2,%3};"
        : "+f"(c[0]), "+f"(c[1]), "+f"(c[2]), "+f"(c[3])
        : "r"(a[0]), "r"(a[1]), "r"(a[2]), "r"(a[3]), "r"(b[0]), "r"(b[1]));
}

// ===================== GEMM mainloop (128x128, K-stage 16) =================
// 256 threads = 8 warps in 2x4 (m x n); warp tile 64x32; acc[4 mtile][4 ntile][4]
// SMEM: stage s: A at s*20480B, B at s*20480+10240B; rows padded to 20 floats.
#define TSTRIDE 20
#define STAGEB  20480
#define SMEM_BYTES (2*STAGEB)

__device__ __forceinline__ void gemm_ml(float (&acc)[4][4][4],
        const float* aP, const float* bP, int nK16,
        const float* smf, uint32_t sb, int tid)
{
    int lane = tid & 31;
    int mB = (tid >> 7) * 64;          // warp>>2
    int nB = ((tid >> 5) & 3) * 32;    // warp&3
    int row = tid >> 1, f8 = (tid & 1) * 8;
    uint32_t sA = sb + (row*TSTRIDE + f8)*4;
    uint32_t sB = sA + 10240;

    // prologue: stage 0
    cp16(sA,      aP);     cp16(sA + 16, aP + 4);
    cp16(sB,      bP);     cp16(sB + 16, bP + 4);
    CP_COMMIT();

    #pragma unroll 1
    for (int s = 0; s < nK16; s++){
        if (s + 1 < nK16){
            uint32_t off = ((s + 1) & 1) * STAGEB;
            const float* an = aP + (s + 1) * 16;
            const float* bn = bP + (s + 1) * 16;
            cp16(sA + off,      an);     cp16(sA + off + 16, an + 4);
            cp16(sB + off,      bn);     cp16(sB + off + 16, bn + 4);
            CP_COMMIT();
            CP_WAIT1();
        } else {
            CP_WAIT0();
        }
        __syncthreads();
        const uint32_t* As = (const uint32_t*)(smf + (s & 1)*(STAGEB/4));
        const uint32_t* Bs = As + 10240/4;
        #pragma unroll
        for (int ks = 0; ks < 16; ks += 8){
            uint32_t a[4][4], b[4][2];
            int c0 = ks + (lane & 3);
            #pragma unroll
            for (int i = 0; i < 4; i++){
                int r = mB + i*16 + (lane >> 2);
                a[i][0] = As[r*TSTRIDE + c0];
                a[i][1] = As[(r+8)*TSTRIDE + c0];
                a[i][2] = As[r*TSTRIDE + c0 + 4];
                a[i][3] = As[(r+8)*TSTRIDE + c0 + 4];
            }
            #pragma unroll
            for (int j = 0; j < 4; j++){
                int n = nB + j*8 + (lane >> 2);
                b[j][0] = Bs[n*TSTRIDE + c0];
                b[j][1] = Bs[n*TSTRIDE + c0 + 4];
            }
            #pragma unroll
            for (int i = 0; i < 4; i++)
                #pragma unroll
                for (int j = 0; j < 4; j++)
                    mma16n8k8(acc[i][j], a[i], b[j]);
        }
        __syncthreads();
    }
}

#define GEMM_PROLOG() \
    extern __shared__ float smf[]; \
    uint32_t sb = smem_to_u32(smf); \
    int tid = threadIdx.x; \
    int row = tid >> 1, f8 = (tid & 1) * 8; \
    float acc[4][4][4]; \
    _Pragma("unroll") for (int i = 0; i < 4; i++) \
    _Pragma("unroll") for (int j = 0; j < 4; j++) \
    _Pragma("unroll") for (int q = 0; q < 4; q++) acc[i][j][q] = 0.f;

#define EPI_VARS() \
    int lane = tid & 31; \
    int mB = (tid >> 7) * 64; \
    int nB = ((tid >> 5) & 3) * 32;

// =========================== small kernels =================================
__global__ __launch_bounds__(256) void k_router(const float* __restrict__ x,
        const float* __restrict__ wr, const float* __restrict__ br){
    int t = blockIdx.x;
    const float* xr = x + (size_t)t*HH;
    double ds = 0.0; float ssq = 0.f;
    for (int i = threadIdx.x; i < HH; i += 256){
        float v = xr[i];
        ds += (double)v * (double)wr[i];
        ssq += v*v;
    }
    __shared__ double sd[256];
    __shared__ float  sf[256];
    sd[threadIdx.x] = ds; sf[threadIdx.x] = ssq;
    __syncthreads();
    for (int o = 128; o > 0; o >>= 1){
        if (threadIdx.x < o){ sd[threadIdx.x] += sd[threadIdx.x+o]; sf[threadIdx.x] += sf[threadIdx.x+o]; }
        __syncthreads();
    }
    if (threadIdx.x == 0){
        g_logits[t] = (float)(sd[0] + (double)br[0]);
        g_r1[t]     = rsqrtf(sf[0]*(1.f/HH) + EPS_F);
    }
}

__global__ __launch_bounds__(1024) void k_topk(){
    __shared__ float s[SS];
    int b = blockIdx.x, tid = threadIdx.x;
    for (int i = tid; i < SS; i += 1024) s[i] = g_logits[b*SS + i];
    __syncthreads();
    for (int k = 2; k <= SS; k <<= 1){
        for (int j = k >> 1; j > 0; j >>= 1){
            for (int i = tid; i < SS; i += 1024){
                int ixj = i ^ j;
                if (ixj > i){
                    float a = s[i], c = s[ixj];
                    bool up = ((i & k) == 0);
                    if ((a > c) == up){ s[i] = c; s[ixj] = a; }
                }
            }
            __syncthreads();
        }
    }
    if (tid == 0) g_thr[b] = s[SS/2];
}

__global__ void k_zero(){ g_nsel = 0; }

__global__ __launch_bounds__(256) void k_compact(){
    int t = blockIdx.x*256 + threadIdx.x;
    if (t < BSZ && g_logits[t] >= g_thr[t/SS]){
        int p = atomicAdd(&g_nsel, 1);
        g_sel[p] = t;
    }
}

__global__ __launch_bounds__(256) void k_r2(){
    int j = blockIdx.x; if (j >= g_nsel) return;
    const float* r = &g_res[(size_t)j*HH];
    float ssq = 0.f;
    for (int i = threadIdx.x; i < HH; i += 256){ float v = r[i]; ssq += v*v; }
    __shared__ float sf[256];
    sf[threadIdx.x] = ssq; __syncthreads();
    for (int o = 128; o > 0; o >>= 1){
        if (threadIdx.x < o) sf[threadIdx.x] += sf[threadIdx.x+o];
        __syncthreads();
    }
    if (threadIdx.x == 0) g_r2[j] = rsqrtf(sf[0]*(1.f/HH) + EPS_F);
}

__global__ __launch_bounds__(256) void k_round(const float* __restrict__ in,
        float* __restrict__ out, int n4){
    int i = blockIdx.x*256 + threadIdx.x;
    if (i < n4){
        float4 v = ((const float4*)in)[i];
        v.x = to_tf32(v.x); v.y = to_tf32(v.y); v.z = to_tf32(v.z); v.w = to_tf32(v.w);
        ((float4*)out)[i] = v;
    }
}

__global__ __launch_bounds__(256) void k_scalewv(const float* __restrict__ Wv,
        const float* __restrict__ n1w){
    int i = blockIdx.x*256 + threadIdx.x;          // float4 index
    int row = i >> 9;                               // HH/4 = 512 per row
    float s = n1w[row];
    float4 v = ((const float4*)Wv)[i];
    v.x = to_tf32(v.x*s); v.y = to_tf32(v.y*s); v.z = to_tf32(v.z*s); v.w = to_tf32(v.w*s);
    ((float4*)g_wvr)[i] = v;
}

// transpose in[R][C] -> out[C][R], value tf32(in[r][c] * (scale? scale[r]:1))
__global__ __launch_bounds__(256) void k_transpose(const float* __restrict__ in,
        float* __restrict__ out, int R, int C, const float* __restrict__ scale){
    __shared__ float ts[32][33];
    int c0 = blockIdx.x*32, r0 = blockIdx.y*32;
    int tx = threadIdx.x, ty = threadIdx.y;       // 32 x 8
    #pragma unroll
    for (int i = 0; i < 32; i += 8){
        int r = r0 + ty + i;
        float v = in[(size_t)r*C + c0 + tx];
        if (scale) v *= scale[r];
        ts[ty+i][tx] = v;
    }
    __syncthreads();
    #pragma unroll
    for (int i = 0; i < 32; i += 8){
        int c = c0 + ty + i;
        out[(size_t)c*R + r0 + tx] = to_tf32(ts[tx][ty+i]);
    }
}

// ====================== mma.sync tf32 GEMM kernels =========================

// WcT[n][m] = sum_k Wo^T[n][k] * Wv'[m][k]   (A rows=woT, B rows=wvr)
__global__ __launch_bounds__(256) void tk_wcomb(){
    int y0 = blockIdx.y*128, x0 = blockIdx.x*128;
    GEMM_PROLOG();
    const float* aP = g_woT + (size_t)(y0+row)*HH + f8;
    const float* bP = g_wvr + (size_t)(x0+row)*HH + f8;
    gemm_ml(acc, aP, bP, HH/16, smf, sb, tid);
    EPI_VARS();
    #pragma unroll
    for (int i = 0; i < 4; i++)
        #pragma unroll
        for (int h = 0; h < 2; h++){
            int r = y0 + mB + i*16 + (lane>>2) + h*8;
            #pragma unroll
            for (int j = 0; j < 4; j++){
                int c = x0 + nB + j*8 + (lane&3)*2;
                g_WcT[(size_t)r*HH + c]     = to_tf32(acc[i][j][h*2]);
                g_WcT[(size_t)r*HH + c + 1] = to_tf32(acc[i][j][h*2+1]);
            }
        }
}

// res = x_sel + r1*(xr_sel @ Wcomb)   : A rows gathered tokens, B rows=WcT
__global__ __launch_bounds__(256) void tk_attn(const float* __restrict__ x){
    int nsel = g_nsel;
    int m0 = blockIdx.y*128; if (m0 >= nsel) return;
    int n0 = blockIdx.x*128;
    GEMM_PROLOG();
    int ja = m0 + row; if (ja >= nsel) ja = nsel - 1;
    const float* aP = g_xr  + (size_t)g_sel[ja]*HH + f8;
    const float* bP = g_WcT + (size_t)(n0+row)*HH + f8;
    gemm_ml(acc, aP, bP, HH/16, smf, sb, tid);
    EPI_VARS();
    #pragma unroll
    for (int i = 0; i < 4; i++)
        #pragma unroll
        for (int h = 0; h < 2; h++){
            int j = m0 + mB + i*16 + (lane>>2) + h*8;
            if (j >= nsel) continue;
            int tok = g_sel[j];
            float r1v = g_r1[tok];
            #pragma unroll
            for (int jj = 0; jj < 4; jj++){
                int c = n0 + nB + jj*8 + (lane&3)*2;
                size_t ob = (size_t)j*HH + c, xb = (size_t)tok*HH + c;
                float v0 = x[xb]   + r1v*acc[i][jj][h*2];
                float v1 = x[xb+1] + r1v*acc[i][jj][h*2+1];
                g_res[ob]   = v0;  g_res[ob+1]  = v1;
                g_resr[ob]  = to_tf32(v0);
                g_resr[ob+1]= to_tf32(v1);
            }
        }
}

// gate: g_hbuf = silu(r2 * (resr @ wgT'))
__global__ __launch_bounds__(256) void tk_gate(){
    int nsel = g_nsel;
    int m0 = blockIdx.y*128; if (m0 >= nsel) return;
    int n0 = blockIdx.x*128;
    GEMM_PROLOG();
    int ja = m0 + row; if (ja >= nsel) ja = nsel - 1;
    const float* aP = g_resr + (size_t)ja*HH + f8;
    const float* bP = g_wgT  + (size_t)(n0+row)*HH + f8;
    gemm_ml(acc, aP, bP, HH/16, smf, sb, tid);
    EPI_VARS();
    #pragma unroll
    for (int i = 0; i < 4; i++)
        #pragma unroll
        for (int h = 0; h < 2; h++){
            int j = m0 + mB + i*16 + (lane>>2) + h*8;
            if (j >= nsel) continue;
            float r2v = g_r2[j];
            #pragma unroll
            for (int jj = 0; jj < 4; jj++){
                int c = n0 + nB + jj*8 + (lane&3)*2;
                size_t ob = (size_t)j*DFFC + c;
                float z0 = r2v*acc[i][jj][h*2];
                float z1 = r2v*acc[i][jj][h*2+1];
                g_hbuf[ob]   = z0 / (1.f + expf(-z0));
                g_hbuf[ob+1] = z1 / (1.f + expf(-z1));
            }
        }
}

// up + combine: g_hbuf = tf32( g_hbuf * (r2 * (resr @ wuT')) )
__global__ __launch_bounds__(256) void tk_up(){
    int nsel = g_nsel;
    int m0 = blockIdx.y*128; if (m0 >= nsel) return;
    int n0 = blockIdx.x*128;
    GEMM_PROLOG();
    int ja = m0 + row; if (ja >= nsel) ja = nsel - 1;
    const float* aP = g_resr + (size_t)ja*HH + f8;
    const float* bP = g_wuT  + (size_t)(n0+row)*HH + f8;
    gemm_ml(acc, aP, bP, HH/16, smf, sb, tid);
    EPI_VARS();
    #pragma unroll
    for (int i = 0; i < 4; i++)
        #pragma unroll
        for (int h = 0; h < 2; h++){
            int j = m0 + mB + i*16 + (lane>>2) + h*8;
            if (j >= nsel) continue;
            float r2v = g_r2[j];
            #pragma unroll
            for (int jj = 0; jj < 4; jj++){
                int c = n0 + nB + jj*8 + (lane&3)*2;
                size_t ob = (size_t)j*DFFC + c;
                float z0 = r2v*acc[i][jj][h*2];
                float z1 = r2v*acc[i][jj][h*2+1];
                g_hbuf[ob]   = to_tf32(g_hbuf[ob]   * z0);
                g_hbuf[ob+1] = to_tf32(g_hbuf[ob+1] * z1);
            }
        }
}

// out[sel] = res + hbuf @ wdT'   (K = 8192)
__global__ __launch_bounds__(256) void tk_down(float* __restrict__ out){
    int nsel = g_nsel;
    int m0 = blockIdx.y*128; if (m0 >= nsel) return;
    int n0 = blockIdx.x*128;
    GEMM_PROLOG();
    int ja = m0 + row; if (ja >= nsel) ja = nsel - 1;
    const float* aP = g_hbuf + (size_t)ja*DFFC + f8;
    const float* bP = g_wdT  + (size_t)(n0+row)*DFFC + f8;
    gemm_ml(acc, aP, bP, DFFC/16, smf, sb, tid);
    EPI_VARS();
    #pragma unroll
    for (int i = 0; i < 4; i++)
        #pragma unroll
        for (int h = 0; h < 2; h++){
            int j = m0 + mB + i*16 + (lane>>2) + h*8;
            if (j >= nsel) continue;
            int tok = g_sel[j];
            #pragma unroll
            for (int jj = 0; jj < 4; jj++){
                int c = n0 + nB + jj*8 + (lane&3)*2;
                size_t rb = (size_t)j*HH + c, ob = (size_t)tok*HH + c;
                out[ob]   = g_res[rb]   + acc[i][jj][h*2];
                out[ob+1] = g_res[rb+1] + acc[i][jj][h*2+1];
            }
        }
}

// ---------------- launch ----------------------------------------------------
extern "C" void kernel_launch(void* const* d_in, const int* in_sizes, int n_in,
                              void* d_out, int out_size){
    const float* x   = (const float*)d_in[0];
    const float* wr  = (const float*)d_in[1];
    const float* br  = (const float*)d_in[2];
    // d_in[3] = Wq, d_in[4] = Wk : dead (softmax over size-1 axis == 1)
    const float* Wv  = (const float*)d_in[5];
    const float* Wo  = (const float*)d_in[6];
    const float* wg  = (const float*)d_in[7];
    const float* wu  = (const float*)d_in[8];
    const float* wd  = (const float*)d_in[9];
    const float* n1w = (const float*)d_in[10];
    const float* n2w = (const float*)d_in[11];
    float* out = (float*)d_out;

    // default output: pass-through tokens
    cudaMemcpyAsync(out, x, (size_t)BSZ*HH*sizeof(float), cudaMemcpyDeviceToDevice, 0);

    k_router <<<BSZ, 256>>>(x, wr, br);
    k_topk   <<<Bb, 1024>>>();
    k_zero   <<<1, 1>>>();
    k_compact<<<BSZ/256, 256>>>();

    // prep: rounded / transposed operands
    float* xr_p; cudaGetSymbolAddress((void**)&xr_p, g_xr);
    k_round    <<<(BSZ*HH/4 + 255)/256, 256>>>(x, xr_p, BSZ*HH/4);
    k_scalewv  <<<(HH*HH/4)/256, 256>>>(Wv, n1w);
    float* woT_p; cudaGetSymbolAddress((void**)&woT_p, g_woT);
    float* wgT_p; cudaGetSymbolAddress((void**)&wgT_p, g_wgT);
    float* wuT_p; cudaGetSymbolAddress((void**)&wuT_p, g_wuT);
    float* wdT_p; cudaGetSymbolAddress((void**)&wdT_p, g_wdT);
    k_transpose<<<dim3(HH/32,  HH/32),   dim3(32,8)>>>(Wo, woT_p, HH,  HH,  nullptr);
    k_transpose<<<dim3(DFFC/32,HH/32),   dim3(32,8)>>>(wg, wgT_p, HH,  DFFC, n2w);
    k_transpose<<<dim3(DFFC/32,HH/32),   dim3(32,8)>>>(wu, wuT_p, HH,  DFFC, n2w);
    k_transpose<<<dim3(HH/32,  DFFC/32), dim3(32,8)>>>(wd, wdT_p, DFFC, HH,  nullptr);

    tk_wcomb<<<dim3(16, 16),  256, SMEM_BYTES>>>();
    tk_attn <<<dim3(16, 128), 256, SMEM_BYTES>>>(x);
    k_r2    <<<BSZ, 256>>>();
    tk_gate <<<dim3(64, 128), 256, SMEM_BYTES>>>();
    tk_up   <<<dim3(64, 128), 256, SMEM_BYTES>>>();
    tk_down <<<dim3(16, 128), 256, SMEM_BYTES>>>(out);
}